// round 14
// baseline (speedup 1.0000x reference)
#include <cuda_runtime.h>
#include <cuda_bf16.h>

#define G   100
#define NF  256
#define NS  256
#define TR  10
#define TRB 10   // G/TR

__device__ float d_M[NF*G*G];
__device__ float d_S[NF*G*G];
__device__ float d_x1h[16*G*G];
__device__ float d_x2h[32*G*G];
__device__ float d_hy[G];
__device__ float d_hx[G];
__device__ float d_g5[32*25];
__device__ float d_cpart[NF*TRB];
__device__ int   d_mi[NS*4];
__device__ float d_mw[NS*4];

// bilinear sample of indicator [lo,hi) on source grid g, half-pixel centers,
// clamped taps (== jax weight renormalization at edges for scale>=1)
__device__ __forceinline__ float bil_profile(int j, int lo, int hi, int g) {
    float s  = (j + 0.5f) * (float)g / 100.0f - 0.5f;
    float fs = floorf(s);
    float w  = s - fs;
    int f0 = (int)fs, f1 = f0 + 1;
    if (f0 < 0) f0 = 0; if (f0 > g-1) f0 = g-1;
    if (f1 < 0) f1 = 0; if (f1 > g-1) f1 = g-1;
    float v0 = (f0 >= lo && f0 < hi) ? 1.f : 0.f;
    float v1 = (f1 >= lo && f1 < hi) ? 1.f : 0.f;
    return v0 * (1.f - w) + v1 * w;
}

// block 0: composed 5x5 kernel g5[o][a][b]; blocks 1..NS: per-sample profile
// meta; block NS+1: human profiles
__global__ void k_setup(const int* ox, const int* oy, const int* ow, const int* oh,
                        const int* pgh, const int* pgw,
                        const float* c1w, const float* c2w) {
    int b = blockIdx.x, t = threadIdx.x;
    if (b == 0) {
        if (t < 32) {
            int o = t;
            float g5l[25];
            #pragma unroll
            for (int i = 0; i < 25; i++) g5l[i] = 0.f;
            for (int m = 0; m < 16; m++) {
                float w1c[9], w2c[9];
                #pragma unroll
                for (int i = 0; i < 9; i++) w1c[i] = c1w[(m*2+1)*9 + i];  // in-ch 1
                #pragma unroll
                for (int i = 0; i < 9; i++) w2c[i] = c2w[(o*16+m)*9 + i];
                #pragma unroll
                for (int ky = 0; ky < 3; ky++)
                #pragma unroll
                for (int kx = 0; kx < 3; kx++)
                #pragma unroll
                for (int ey = 0; ey < 3; ey++)
                #pragma unroll
                for (int ex = 0; ex < 3; ex++) {
                    int a = 4 - (ky + ey), bb = 4 - (kx + ex);
                    g5l[a*5 + bb] += w1c[ky*3+kx] * w2c[ey*3+ex];
                }
            }
            for (int i = 0; i < 25; i++) d_g5[o*25 + i] = g5l[i];
        }
    } else if (b <= NS) {
        __shared__ float py[G], px[G];
        int s = b - 1;
        int gh = *pgh, gw = *pgw;
        if (t < G) {
            py[t] = bil_profile(t, oy[s], oy[s] + oh[s], gh);
            px[t] = bil_profile(t, ox[s], ox[s] + ow[s], gw);
        }
        __syncthreads();
        if (t == 0) {
            int iL = -1, iR = -1;
            for (int i = 0; i < G; i++) if (py[i] != 0.f) { if (iL < 0) iL = i; iR = i; }
            float ay = 0.f, by = 0.f;
            if (iL >= 0) { ay = py[iL]; by = (iR > iL) ? py[iR] : 0.f; } else { iL = 0; iR = 0; }
            d_mi[s*4+0] = iL; d_mi[s*4+1] = iR; d_mw[s*4+0] = ay; d_mw[s*4+1] = by;
            int jL = -1, jR = -1;
            for (int j = 0; j < G; j++) if (px[j] != 0.f) { if (jL < 0) jL = j; jR = j; }
            float ax = 0.f, bx = 0.f;
            if (jL >= 0) { ax = px[jL]; bx = (jR > jL) ? px[jR] : 0.f; } else { jL = 0; jR = 0; }
            d_mi[s*4+2] = jL; d_mi[s*4+3] = jR; d_mw[s*4+2] = ax; d_mw[s*4+3] = bx;
        }
    } else {
        int gh = *pgh, gw = *pgw;
        if (t < G) {
            d_hy[t] = bil_profile(t, 0, 100, gh);
            d_hx[t] = bil_profile(t, 0, 100, gw);
        }
    }
}

// x1h = conv1((human,0)) + b1 ; human = hy (outer) hx
__global__ void k_x1h(const float* c1w, const float* c1b) {
    __shared__ float sw[16*9], sb[16];
    int y = blockIdx.x, t = threadIdx.x;
    for (int i = t; i < 144; i += 128) sw[i] = c1w[(i/9)*18 + (i%9)];  // in-ch 0
    if (t < 16) sb[t] = c1b[t];
    __syncthreads();
    if (t < G) {
        int x = t;
        float hyv[3], hxv[3];
        #pragma unroll
        for (int a = 0; a < 3; a++) {
            int yy = y - 1 + a; hyv[a] = (yy >= 0 && yy < G) ? d_hy[yy] : 0.f;
            int xx = x - 1 + a; hxv[a] = (xx >= 0 && xx < G) ? d_hx[xx] : 0.f;
        }
        for (int m = 0; m < 16; m++) {
            float acc = sb[m];
            #pragma unroll
            for (int a = 0; a < 3; a++)
            #pragma unroll
            for (int bb = 0; bb < 3; bb++) acc += sw[m*9 + a*3 + bb] * hyv[a] * hxv[bb];
            d_x1h[(m*G + y)*G + x] = acc;
        }
    }
}

// x2h = conv2(x1h) + b2
__global__ void k_x2h(const float* c2w, const float* c2b) {
    __shared__ float sw2[32*16*9];
    __shared__ float sb2[32];
    __shared__ float sx1[16*3*G];
    int y = blockIdx.x, t = threadIdx.x;
    for (int i = t; i < 4608; i += 128) sw2[i] = c2w[i];
    if (t < 32) sb2[t] = c2b[t];
    for (int i = t; i < 16*3*G; i += 128) {
        int m = i / (3*G), rem = i % (3*G), a = rem / G, x = rem % G;
        int yy = y - 1 + a;
        sx1[i] = (yy >= 0 && yy < G) ? d_x1h[(m*G + yy)*G + x] : 0.f;
    }
    __syncthreads();
    if (t < G) {
        int x = t;
        float acc[32];
        #pragma unroll
        for (int o = 0; o < 32; o++) acc[o] = sb2[o];
        for (int m = 0; m < 16; m++) {
            float v[9];
            #pragma unroll
            for (int a = 0; a < 3; a++)
            #pragma unroll
            for (int bb = 0; bb < 3; bb++) {
                int xx = x - 1 + bb;
                v[a*3+bb] = (xx >= 0 && xx < G) ? sx1[(m*3 + a)*G + xx] : 0.f;
            }
            #pragma unroll
            for (int o = 0; o < 32; o++) {
                float s0 = acc[o];
                #pragma unroll
                for (int kk = 0; kk < 9; kk++) s0 += sw2[(o*16+m)*9 + kk] * v[kk];
                acc[o] = s0;
            }
        }
        for (int o = 0; o < 32; o++) d_x2h[(o*G + y)*G + x] = acc[o];
    }
}

// main kernel: M~[f,i,j] = sum_o sum_{a,b in 0..4} g5[o,a,b] * P[f,o,i-2+a,j-2+b]
// (zero-padded P) + fused partial const dot <P[f], x2h>
__global__ void __launch_bounds__(128) k_M(const float* __restrict__ P) {
    __shared__ float smP[14][104];
    __shared__ float smX[TR][G];
    __shared__ float smG[32*25];
    __shared__ float sred[128];
    int rt = blockIdx.x, f = blockIdx.y, t = threadIdx.x;
    int r0 = rt * TR;
    for (int i = t; i < 800; i += 128) smG[i] = d_g5[i];
    float acc[TR];
    #pragma unroll
    for (int r = 0; r < TR; r++) acc[r] = 0.f;
    float cacc = 0.f;
    const float* Pf = P + (size_t)f * 32 * G * G;
    for (int o = 0; o < 32; o++) {
        __syncthreads();
        for (int i = t; i < 14*104; i += 128) {
            int rr = i / 104, c = i % 104;
            int gr = r0 - 2 + rr, gc = c - 2;
            float v = 0.f;
            if (gr >= 0 && gr < G && gc >= 0 && gc < G) v = Pf[(o*G + gr)*G + gc];
            smP[rr][c] = v;
        }
        for (int i = t; i < TR*G; i += 128) {
            int rr = i / G, c = i % G;
            smX[rr][c] = d_x2h[(o*G + r0 + rr)*G + c];
        }
        __syncthreads();
        if (t < G) {
            int j = t;
            #pragma unroll
            for (int v = 0; v < 5; v++) {
                float col[14];
                #pragma unroll
                for (int rr = 0; rr < 14; rr++) col[rr] = smP[rr][j + v];
                #pragma unroll
                for (int u = 0; u < 5; u++) {
                    float g = smG[o*25 + u*5 + v];
                    #pragma unroll
                    for (int r = 0; r < TR; r++) acc[r] += g * col[r + u];
                }
            }
            #pragma unroll
            for (int r = 0; r < TR; r++) cacc += smP[r + 2][j + 2] * smX[r][j];
        }
    }
    if (t < G) {
        int j = t;
        for (int r = 0; r < TR; r++) d_M[(f*G + (r0 + r))*G + j] = acc[r];
    }
    sred[t] = (t < G) ? cacc : 0.f;
    __syncthreads();
    for (int s = 64; s > 0; s >>= 1) { if (t < s) sred[t] += sred[t + s]; __syncthreads(); }
    if (t == 0) d_cpart[f*TRB + rt] = sred[0];
}

// exact border corrections for the intermediate (t) crop: M = M~ - E on the
// 1-pixel frame. Row corrections use t_ext rows -1/G (w2 ey=0/2 vs P rows
// 0/G-1), col corrections use t_ext cols -1/G restricted to p in [0,G)
// (corners live in the row arrays -> no double count).
__global__ void k_border(const float* __restrict__ P, const float* c1w, const float* c2w) {
    __shared__ float TN[16][102], TS[16][102], TW[16][100], TE[16][100];
    int f = blockIdx.x, t = threadIdx.x;
    const float* Pf = P + (size_t)f * 32 * G * G;
    for (int i = t; i < 16*102; i += 128) {
        int m = i / 102, qq = i % 102, q = qq - 1;
        float an = 0.f, as = 0.f;
        for (int o = 0; o < 32; o++) {
            #pragma unroll
            for (int ex = 0; ex < 3; ex++) {
                int cc = q - ex + 1;
                if (cc >= 0 && cc < G) {
                    an += c2w[(o*16+m)*9 + 0*3 + ex] * Pf[(o*G + 0)*G + cc];
                    as += c2w[(o*16+m)*9 + 2*3 + ex] * Pf[(o*G + (G-1))*G + cc];
                }
            }
        }
        TN[m][qq] = an; TS[m][qq] = as;
    }
    for (int i = t; i < 16*100; i += 128) {
        int m = i / 100, p = i % 100;
        float aw = 0.f, ae = 0.f;
        for (int o = 0; o < 32; o++) {
            #pragma unroll
            for (int ey = 0; ey < 3; ey++) {
                int rr = p - ey + 1;
                if (rr >= 0 && rr < G) {
                    aw += c2w[(o*16+m)*9 + ey*3 + 0] * Pf[(o*G + rr)*G + 0];
                    ae += c2w[(o*16+m)*9 + ey*3 + 2] * Pf[(o*G + rr)*G + (G-1)];
                }
            }
        }
        TW[m][p] = aw; TE[m][p] = ae;
    }
    __syncthreads();
    if (t < G) {
        int j = t;
        float ct = 0.f, cb = 0.f;
        for (int m = 0; m < 16; m++) {
            #pragma unroll
            for (int kx = 0; kx < 3; kx++) {
                int qq = j - kx + 2;
                ct += c1w[(m*2+1)*9 + 2*3 + kx] * TN[m][qq];
                cb += c1w[(m*2+1)*9 + 0*3 + kx] * TS[m][qq];
            }
        }
        d_M[(f*G + 0)*G + j]     -= ct;
        d_M[(f*G + (G-1))*G + j] -= cb;
    }
    __syncthreads();
    if (t < G) {
        int i = t;
        float cl = 0.f, cr = 0.f;
        for (int m = 0; m < 16; m++) {
            #pragma unroll
            for (int ky = 0; ky < 3; ky++) {
                int p = i - ky + 1;
                if (p >= 0 && p < G) {
                    cl += c1w[(m*2+1)*9 + ky*3 + 2] * TW[m][p];
                    cr += c1w[(m*2+1)*9 + ky*3 + 0] * TE[m][p];
                }
            }
        }
        d_M[(f*G + i)*G + 0]     -= cl;
        d_M[(f*G + i)*G + (G-1)] -= cr;
    }
}

// inclusive 2-D SAT per f, in shared memory (padded rows -> conflict-free)
__global__ void k_prefix() {
    __shared__ float sm[G][G + 1];
    int f = blockIdx.x, t = threadIdx.x;
    for (int i = t; i < G*G; i += 128) sm[i / G][i % G] = d_M[f*G*G + i];
    __syncthreads();
    if (t < G) {
        float r = 0.f;
        for (int j = 0; j < G; j++) { r += sm[t][j]; sm[t][j] = r; }
    }
    __syncthreads();
    if (t < G) {
        float r = 0.f;
        for (int i = 0; i < G; i++) { r += sm[i][t]; sm[i][t] = r; }
    }
    __syncthreads();
    for (int i = t; i < G*G; i += 128) d_S[f*G*G + i] = sm[i / G][i % G];
}

__device__ __forceinline__ float satv(const float* base, int i, int j) {
    return (i < 0 || j < 0) ? 0.f : base[i*G + j];
}
__device__ __forceinline__ float rectsum(const float* base, int a, int b, int c, int d) {
    if (a > b || c > d) return 0.f;
    return satv(base, b, d) - satv(base, a-1, d) - satv(base, b, c-1) + satv(base, a-1, c-1);
}

// out[s,f] = const[f] + py^T M_f px via SAT (profiles: alpha ends + interior ones)
__global__ void k_eval(const float* __restrict__ pb, float* __restrict__ out) {
    int s = blockIdx.x, f = threadIdx.x;
    int   iL = d_mi[s*4+0], iR = d_mi[s*4+1], jL = d_mi[s*4+2], jR = d_mi[s*4+3];
    float ay = d_mw[s*4+0], by = d_mw[s*4+1], ax = d_mw[s*4+2], bx = d_mw[s*4+3];
    const float* base = d_S + (size_t)f * G * G;
    int i0 = iL + 1, i1 = iR - 1, j0 = jL + 1, j1 = jR - 1;
    float acc = rectsum(base, i0, i1, j0, j1);
    acc += ay * rectsum(base, iL, iL, j0, j1) + by * rectsum(base, iR, iR, j0, j1);
    acc += ax * rectsum(base, i0, i1, jL, jL) + bx * rectsum(base, i0, i1, jR, jR);
    acc += ay*ax * rectsum(base, iL, iL, jL, jL) + ay*bx * rectsum(base, iL, iL, jR, jR)
         + by*ax * rectsum(base, iR, iR, jL, jL) + by*bx * rectsum(base, iR, iR, jR, jR);
    float cs = pb[f];
    #pragma unroll
    for (int r = 0; r < TRB; r++) cs += d_cpart[f*TRB + r];
    out[s*NF + f] = cs + acc;
}

extern "C" void kernel_launch(void* const* d_in, const int* in_sizes, int n_in,
                              void* d_out, int out_size) {
    const int*   ox  = (const int*)d_in[0];
    const int*   oy  = (const int*)d_in[1];
    const int*   ow  = (const int*)d_in[2];
    const int*   oh  = (const int*)d_in[3];
    const int*   gh  = (const int*)d_in[4];
    const int*   gw  = (const int*)d_in[5];
    const float* c1w = (const float*)d_in[6];
    const float* c1b = (const float*)d_in[7];
    const float* c2w = (const float*)d_in[8];
    const float* c2b = (const float*)d_in[9];
    const float* pw  = (const float*)d_in[10];
    const float* pbb = (const float*)d_in[11];
    float* out = (float*)d_out;

    k_setup <<<NS + 2, 128>>>(ox, oy, ow, oh, gh, gw, c1w, c2w);
    k_x1h   <<<G, 128>>>(c1w, c1b);
    k_x2h   <<<G, 128>>>(c2w, c2b);
    k_M     <<<dim3(G/TR, NF), 128>>>(pw);
    k_border<<<NF, 128>>>(pw, c1w, c2w);
    k_prefix<<<NF, 128>>>();
    k_eval  <<<NS, NF>>>(pbb, out);
}

// round 16
// speedup vs baseline: 1.1254x; 1.1254x over previous
#include <cuda_runtime.h>
#include <cuda_bf16.h>

#define G    100
#define NF   256
#define NS   256
#define TR2  20
#define NRT  5    // G/TR2
#define SMW  (24*104 + 4)   // padded plane: stray edge read at 2496 hits zeros

__device__ float d_M[NF*G*G];
__device__ float d_S[NF*G*G];
__device__ float d_x1h[16*G*G];
__device__ float d_x2h[32*G*G];
__device__ float d_hy[G];
__device__ float d_hx[G];
__device__ float d_g5[32*25];
__device__ float d_cpart[NF*NRT];
__device__ int   d_mi[NS*4];
__device__ float d_mw[NS*4];

__device__ __forceinline__ unsigned long long ffma2(unsigned long long a,
                                                    unsigned long long b,
                                                    unsigned long long c) {
    unsigned long long d;
    asm("fma.rn.f32x2 %0, %1, %2, %3;" : "=l"(d) : "l"(a), "l"(b), "l"(c));
    return d;
}
__device__ __forceinline__ float f2lo(unsigned long long v) {
    return __uint_as_float((unsigned)(v & 0xFFFFFFFFULL));
}
__device__ __forceinline__ float f2hi(unsigned long long v) {
    return __uint_as_float((unsigned)(v >> 32));
}

// bilinear sample of indicator [lo,hi) on source grid g, half-pixel centers,
// clamped taps (== jax weight renormalization at edges for scale>=1)
__device__ __forceinline__ float bil_profile(int j, int lo, int hi, int g) {
    float s  = (j + 0.5f) * (float)g / 100.0f - 0.5f;
    float fs = floorf(s);
    float w  = s - fs;
    int f0 = (int)fs, f1 = f0 + 1;
    if (f0 < 0) f0 = 0; if (f0 > g-1) f0 = g-1;
    if (f1 < 0) f1 = 0; if (f1 > g-1) f1 = g-1;
    float v0 = (f0 >= lo && f0 < hi) ? 1.f : 0.f;
    float v1 = (f1 >= lo && f1 < hi) ? 1.f : 0.f;
    return v0 * (1.f - w) + v1 * w;
}

// block 0: composed 5x5 kernel; blocks 1..NS: per-sample profile meta;
// block NS+1: human profiles
__global__ void k_setup(const int* ox, const int* oy, const int* ow, const int* oh,
                        const int* pgh, const int* pgw,
                        const float* c1w, const float* c2w) {
    int b = blockIdx.x, t = threadIdx.x;
    if (b == 0) {
        if (t < 32) {
            int o = t;
            float g5l[25];
            #pragma unroll
            for (int i = 0; i < 25; i++) g5l[i] = 0.f;
            for (int m = 0; m < 16; m++) {
                float w1c[9], w2c[9];
                #pragma unroll
                for (int i = 0; i < 9; i++) w1c[i] = c1w[(m*2+1)*9 + i];  // in-ch 1
                #pragma unroll
                for (int i = 0; i < 9; i++) w2c[i] = c2w[(o*16+m)*9 + i];
                #pragma unroll
                for (int ky = 0; ky < 3; ky++)
                #pragma unroll
                for (int kx = 0; kx < 3; kx++)
                #pragma unroll
                for (int ey = 0; ey < 3; ey++)
                #pragma unroll
                for (int ex = 0; ex < 3; ex++) {
                    int a = 4 - (ky + ey), bb = 4 - (kx + ex);
                    g5l[a*5 + bb] += w1c[ky*3+kx] * w2c[ey*3+ex];
                }
            }
            for (int i = 0; i < 25; i++) d_g5[o*25 + i] = g5l[i];
        }
    } else if (b <= NS) {
        __shared__ float py[G], px[G];
        int s = b - 1;
        int gh = *pgh, gw = *pgw;
        if (t < G) {
            py[t] = bil_profile(t, oy[s], oy[s] + oh[s], gh);
            px[t] = bil_profile(t, ox[s], ox[s] + ow[s], gw);
        }
        __syncthreads();
        if (t == 0) {
            int iL = -1, iR = -1;
            for (int i = 0; i < G; i++) if (py[i] != 0.f) { if (iL < 0) iL = i; iR = i; }
            float ay = 0.f, by = 0.f;
            if (iL >= 0) { ay = py[iL]; by = (iR > iL) ? py[iR] : 0.f; } else { iL = 0; iR = 0; }
            d_mi[s*4+0] = iL; d_mi[s*4+1] = iR; d_mw[s*4+0] = ay; d_mw[s*4+1] = by;
            int jL = -1, jR = -1;
            for (int j = 0; j < G; j++) if (px[j] != 0.f) { if (jL < 0) jL = j; jR = j; }
            float ax = 0.f, bx = 0.f;
            if (jL >= 0) { ax = px[jL]; bx = (jR > jL) ? px[jR] : 0.f; } else { jL = 0; jR = 0; }
            d_mi[s*4+2] = jL; d_mi[s*4+3] = jR; d_mw[s*4+2] = ax; d_mw[s*4+3] = bx;
        }
    } else {
        int gh = *pgh, gw = *pgw;
        if (t < G) {
            d_hy[t] = bil_profile(t, 0, 100, gh);
            d_hx[t] = bil_profile(t, 0, 100, gw);
        }
    }
}

// x1h = conv1((human,0)) + b1 ; human = hy (outer) hx
__global__ void k_x1h(const float* c1w, const float* c1b) {
    __shared__ float sw[16*9], sb[16];
    int y = blockIdx.x, t = threadIdx.x;
    for (int i = t; i < 144; i += 128) sw[i] = c1w[(i/9)*18 + (i%9)];  // in-ch 0
    if (t < 16) sb[t] = c1b[t];
    __syncthreads();
    if (t < G) {
        int x = t;
        float hyv[3], hxv[3];
        #pragma unroll
        for (int a = 0; a < 3; a++) {
            int yy = y - 1 + a; hyv[a] = (yy >= 0 && yy < G) ? d_hy[yy] : 0.f;
            int xx = x - 1 + a; hxv[a] = (xx >= 0 && xx < G) ? d_hx[xx] : 0.f;
        }
        for (int m = 0; m < 16; m++) {
            float acc = sb[m];
            #pragma unroll
            for (int a = 0; a < 3; a++)
            #pragma unroll
            for (int bb = 0; bb < 3; bb++) acc += sw[m*9 + a*3 + bb] * hyv[a] * hxv[bb];
            d_x1h[(m*G + y)*G + x] = acc;
        }
    }
}

// x2h = conv2(x1h) + b2
__global__ void k_x2h(const float* c2w, const float* c2b) {
    __shared__ float sw2[32*16*9];
    __shared__ float sb2[32];
    __shared__ float sx1[16*3*G];
    int y = blockIdx.x, t = threadIdx.x;
    for (int i = t; i < 4608; i += 128) sw2[i] = c2w[i];
    if (t < 32) sb2[t] = c2b[t];
    for (int i = t; i < 16*3*G; i += 128) {
        int m = i / (3*G), rem = i % (3*G), a = rem / G, x = rem % G;
        int yy = y - 1 + a;
        sx1[i] = (yy >= 0 && yy < G) ? d_x1h[(m*G + yy)*G + x] : 0.f;
    }
    __syncthreads();
    if (t < G) {
        int x = t;
        float acc[32];
        #pragma unroll
        for (int o = 0; o < 32; o++) acc[o] = sb2[o];
        for (int m = 0; m < 16; m++) {
            float v[9];
            #pragma unroll
            for (int a = 0; a < 3; a++)
            #pragma unroll
            for (int bb = 0; bb < 3; bb++) {
                int xx = x - 1 + bb;
                v[a*3+bb] = (xx >= 0 && xx < G) ? sx1[(m*3 + a)*G + xx] : 0.f;
            }
            #pragma unroll
            for (int o = 0; o < 32; o++) {
                float s0 = acc[o];
                #pragma unroll
                for (int kk = 0; kk < 9; kk++) s0 += sw2[(o*16+m)*9 + kk] * v[kk];
                acc[o] = s0;
            }
        }
        for (int o = 0; o < 32; o++) d_x2h[(o*G + y)*G + x] = acc[o];
    }
}

// ---------------------------------------------------------------------------
// k_M: M~[f,i,j] = sum_o sum_{u,v} g5[o,u,v] * P[f,o,i-2+u,j-2+v] (zero-pad)
// + fused partial const dot <P[f], x2h>. f32x2-packed, TR2=20 rows/block,
// double-buffered smem with a byte-shifted copy for odd-column alignment.
// smN[rr*104 + 2 + x] = P[x]; smS[rr*104 + 3 + x] = P[x]. Even j reads smN at
// rr*104 + j; odd j reads smS at rr*104 + j+1. Planes padded (SMW) so the
// j=99,rr=23 c4 read at flat index 2496 returns 0.
// ---------------------------------------------------------------------------
__global__ void __launch_bounds__(256) k_M(const float* __restrict__ P) {
    __shared__ float  smN[2][SMW];
    __shared__ float  smS[2][SMW];
    __shared__ float2 sg01[32*5];
    __shared__ float2 sg23[32*5];
    __shared__ float  sg4[32*5];
    __shared__ float  sred[256];
    int rt = blockIdx.x, f = blockIdx.y, t = threadIdx.x;
    int r0 = rt * TR2;
    const float* Pf = P + (size_t)f * 32 * G * G;

    for (int i = t; i < 160; i += 256) {
        int o = i / 5, u = i % 5;
        const float* g = d_g5 + o*25 + u*5;
        sg01[i] = make_float2(g[0], g[1]);
        sg23[i] = make_float2(g[2], g[3]);
        sg4[i]  = g[4];
    }
    for (int i = t; i < SMW; i += 256) {
        smN[0][i] = 0.f; smN[1][i] = 0.f; smS[0][i] = 0.f; smS[1][i] = 0.f;
    }
    __syncthreads();

    // loader chunk metadata (600 float4 chunks over 256 threads -> <=3 each)
    int  cg[3], crw[3];
    bool cv[3];
    #pragma unroll
    for (int c = 0; c < 3; c++) {
        int idx = t + c*256;
        int row = idx / 25, c4 = idx % 25;
        int gr  = r0 - 2 + row;
        cv[c]  = (idx < 600) && (gr >= 0) && (gr < G);
        cg[c]  = gr*G + c4*4;
        crw[c] = row*104 + 2 + c4*4;
    }

    auto load_buf = [&](int buf, int o) {
        const float* src = Pf + o*G*G;
        #pragma unroll
        for (int c = 0; c < 3; c++) {
            if (cv[c]) {
                float4 v = *(const float4*)(src + cg[c]);
                *(float2*)&smN[buf][crw[c]]     = make_float2(v.x, v.y);
                *(float2*)&smN[buf][crw[c] + 2] = make_float2(v.z, v.w);
                smS[buf][crw[c] + 1] = v.x;
                *(float2*)&smS[buf][crw[c] + 2] = make_float2(v.y, v.z);
                smS[buf][crw[c] + 4] = v.w;
            }
        }
    };

    load_buf(0, 0);

    bool act = t < 200;
    int h = t / 100, j = t % 100;
    bool odd = (j & 1);
    int rowbase = h*10*104 + (odd ? (j + 1) : j);

    unsigned long long acc2[10];
    float accS[10];
    #pragma unroll
    for (int r = 0; r < 10; r++) { acc2[r] = 0ULL; accS[r] = 0.f; }
    float cacc = 0.f;

    __syncthreads();

    for (int o = 0; o < 32; o++) {
        int buf = o & 1;
        if (o + 1 < 32) load_buf(buf ^ 1, o + 1);
        if (act) {
            unsigned long long g01r[5], g23r[5];
            float g4r[5];
            #pragma unroll
            for (int u = 0; u < 5; u++) {
                g01r[u] = *(const unsigned long long*)&sg01[o*5 + u];
                g23r[u] = *(const unsigned long long*)&sg23[o*5 + u];
                g4r[u]  = sg4[o*5 + u];
            }
            const float* base = odd ? &smS[buf][rowbase] : &smN[buf][rowbase];
            const float* x2b  = d_x2h + (o*G + r0 + h*10)*G + j;
            #pragma unroll
            for (int k = 0; k < 14; k++) {
                unsigned long long p01 = *(const unsigned long long*)(base + k*104);
                unsigned long long p23 = *(const unsigned long long*)(base + k*104 + 2);
                float c4v = base[k*104 + 4];
                #pragma unroll
                for (int u = 0; u < 5; u++) {
                    int r = k - u;
                    if (r >= 0 && r < 10) {
                        acc2[r] = ffma2(g01r[u], p01, acc2[r]);
                        acc2[r] = ffma2(g23r[u], p23, acc2[r]);
                        accS[r] = fmaf(g4r[u], c4v, accS[r]);
                    }
                }
                if (k >= 2 && k <= 11) {
                    // center value P[row][j] = lo half of p23
                    cacc = fmaf(f2lo(p23), x2b[(k - 2)*G], cacc);
                }
            }
        }
        __syncthreads();
    }

    if (act) {
        #pragma unroll
        for (int r = 0; r < 10; r++)
            d_M[(f*G + r0 + h*10 + r)*G + j] = f2lo(acc2[r]) + f2hi(acc2[r]) + accS[r];
    }
    sred[t] = act ? cacc : 0.f;
    __syncthreads();
    for (int s = 128; s > 0; s >>= 1) { if (t < s) sred[t] += sred[t + s]; __syncthreads(); }
    if (t == 0) d_cpart[f*NRT + rt] = sred[0];
}

// exact border corrections for the intermediate crop (c2w staged in smem)
__global__ void k_border(const float* __restrict__ P, const float* c1w, const float* c2w) {
    __shared__ float TN[16][102], TS[16][102], TW[16][100], TE[16][100];
    __shared__ float sc2[32*16*9];
    int f = blockIdx.x, t = threadIdx.x;
    const float* Pf = P + (size_t)f * 32 * G * G;
    for (int i = t; i < 4608; i += 128) sc2[i] = c2w[i];
    __syncthreads();
    for (int i = t; i < 16*102; i += 128) {
        int m = i / 102, qq = i % 102, q = qq - 1;
        float an = 0.f, as = 0.f;
        for (int o = 0; o < 32; o++) {
            #pragma unroll
            for (int ex = 0; ex < 3; ex++) {
                int cc = q - ex + 1;
                if (cc >= 0 && cc < G) {
                    an += sc2[(o*16+m)*9 + 0*3 + ex] * Pf[(o*G + 0)*G + cc];
                    as += sc2[(o*16+m)*9 + 2*3 + ex] * Pf[(o*G + (G-1))*G + cc];
                }
            }
        }
        TN[m][qq] = an; TS[m][qq] = as;
    }
    for (int i = t; i < 16*100; i += 128) {
        int m = i / 100, p = i % 100;
        float aw = 0.f, ae = 0.f;
        for (int o = 0; o < 32; o++) {
            #pragma unroll
            for (int ey = 0; ey < 3; ey++) {
                int rr = p - ey + 1;
                if (rr >= 0 && rr < G) {
                    aw += sc2[(o*16+m)*9 + ey*3 + 0] * Pf[(o*G + rr)*G + 0];
                    ae += sc2[(o*16+m)*9 + ey*3 + 2] * Pf[(o*G + rr)*G + (G-1)];
                }
            }
        }
        TW[m][p] = aw; TE[m][p] = ae;
    }
    __syncthreads();
    if (t < G) {
        int j = t;
        float ct = 0.f, cb = 0.f;
        for (int m = 0; m < 16; m++) {
            #pragma unroll
            for (int kx = 0; kx < 3; kx++) {
                int qq = j - kx + 2;
                ct += c1w[(m*2+1)*9 + 2*3 + kx] * TN[m][qq];
                cb += c1w[(m*2+1)*9 + 0*3 + kx] * TS[m][qq];
            }
        }
        d_M[(f*G + 0)*G + j]     -= ct;
        d_M[(f*G + (G-1))*G + j] -= cb;
    }
    __syncthreads();
    if (t < G) {
        int i = t;
        float cl = 0.f, cr = 0.f;
        for (int m = 0; m < 16; m++) {
            #pragma unroll
            for (int ky = 0; ky < 3; ky++) {
                int p = i - ky + 1;
                if (p >= 0 && p < G) {
                    cl += c1w[(m*2+1)*9 + ky*3 + 2] * TW[m][p];
                    cr += c1w[(m*2+1)*9 + ky*3 + 0] * TE[m][p];
                }
            }
        }
        d_M[(f*G + i)*G + 0]     -= cl;
        d_M[(f*G + i)*G + (G-1)] -= cr;
    }
}

// inclusive 2-D SAT per f, in shared memory
__global__ void k_prefix() {
    __shared__ float sm[G][G + 1];
    int f = blockIdx.x, t = threadIdx.x;
    for (int i = t; i < G*G; i += 128) sm[i / G][i % G] = d_M[f*G*G + i];
    __syncthreads();
    if (t < G) {
        float r = 0.f;
        for (int j = 0; j < G; j++) { r += sm[t][j]; sm[t][j] = r; }
    }
    __syncthreads();
    if (t < G) {
        float r = 0.f;
        for (int i = 0; i < G; i++) { r += sm[i][t]; sm[i][t] = r; }
    }
    __syncthreads();
    for (int i = t; i < G*G; i += 128) d_S[f*G*G + i] = sm[i / G][i % G];
}

__device__ __forceinline__ float satv(const float* base, int i, int j) {
    return (i < 0 || j < 0) ? 0.f : base[i*G + j];
}
__device__ __forceinline__ float rectsum(const float* base, int a, int b, int c, int d) {
    if (a > b || c > d) return 0.f;
    return satv(base, b, d) - satv(base, a-1, d) - satv(base, b, c-1) + satv(base, a-1, c-1);
}

// out[s,f] = const[f] + py^T M_f px via SAT
__global__ void k_eval(const float* __restrict__ pb, float* __restrict__ out) {
    int s = blockIdx.x, f = threadIdx.x;
    int   iL = d_mi[s*4+0], iR = d_mi[s*4+1], jL = d_mi[s*4+2], jR = d_mi[s*4+3];
    float ay = d_mw[s*4+0], by = d_mw[s*4+1], ax = d_mw[s*4+2], bx = d_mw[s*4+3];
    const float* base = d_S + (size_t)f * G * G;
    int i0 = iL + 1, i1 = iR - 1, j0 = jL + 1, j1 = jR - 1;
    float acc = rectsum(base, i0, i1, j0, j1);
    acc += ay * rectsum(base, iL, iL, j0, j1) + by * rectsum(base, iR, iR, j0, j1);
    acc += ax * rectsum(base, i0, i1, jL, jL) + bx * rectsum(base, i0, i1, jR, jR);
    acc += ay*ax * rectsum(base, iL, iL, jL, jL) + ay*bx * rectsum(base, iL, iL, jR, jR)
         + by*ax * rectsum(base, iR, iR, jL, jL) + by*bx * rectsum(base, iR, iR, jR, jR);
    float cs = pb[f];
    #pragma unroll
    for (int r = 0; r < NRT; r++) cs += d_cpart[f*NRT + r];
    out[s*NF + f] = cs + acc;
}

extern "C" void kernel_launch(void* const* d_in, const int* in_sizes, int n_in,
                              void* d_out, int out_size) {
    const int*   ox  = (const int*)d_in[0];
    const int*   oy  = (const int*)d_in[1];
    const int*   ow  = (const int*)d_in[2];
    const int*   oh  = (const int*)d_in[3];
    const int*   gh  = (const int*)d_in[4];
    const int*   gw  = (const int*)d_in[5];
    const float* c1w = (const float*)d_in[6];
    const float* c1b = (const float*)d_in[7];
    const float* c2w = (const float*)d_in[8];
    const float* c2b = (const float*)d_in[9];
    const float* pw  = (const float*)d_in[10];
    const float* pbb = (const float*)d_in[11];
    float* out = (float*)d_out;

    k_setup <<<NS + 2, 128>>>(ox, oy, ow, oh, gh, gw, c1w, c2w);
    k_x1h   <<<G, 128>>>(c1w, c1b);
    k_x2h   <<<G, 128>>>(c2w, c2b);
    k_M     <<<dim3(NRT, NF), 256>>>(pw);
    k_border<<<NF, 128>>>(pw, c1w, c2w);
    k_prefix<<<NF, 128>>>();
    k_eval  <<<NS, NF>>>(pbb, out);
}

// round 17
// speedup vs baseline: 2.7621x; 2.4543x over previous
#include <cuda_runtime.h>
#include <cuda_bf16.h>

#define G    100
#define NF   256
#define NS   256
#define TR2  20
#define NRT  5    // G/TR2
#define SMW  (24*104 + 4)   // padded plane: stray edge read at 2496 hits zeros

__device__ float d_M[NF*G*G];
__device__ float d_S[NF*G*G];
__device__ float d_x1h[16*G*G];
__device__ float d_x2h[32*G*G];
__device__ float d_hy[G];
__device__ float d_hx[G];
__device__ float d_g5[32*25];
__device__ float d_cpart[NF*NRT];
__device__ int   d_mi[NS*4];
__device__ float d_mw[NS*4];

__device__ __forceinline__ unsigned long long ffma2(unsigned long long a,
                                                    unsigned long long b,
                                                    unsigned long long c) {
    unsigned long long d;
    asm("fma.rn.f32x2 %0, %1, %2, %3;" : "=l"(d) : "l"(a), "l"(b), "l"(c));
    return d;
}
__device__ __forceinline__ float f2lo(unsigned long long v) {
    return __uint_as_float((unsigned)(v & 0xFFFFFFFFULL));
}
__device__ __forceinline__ float f2hi(unsigned long long v) {
    return __uint_as_float((unsigned)(v >> 32));
}

// bilinear sample of indicator [lo,hi) on source grid g, half-pixel centers,
// clamped taps (== jax weight renormalization at edges for scale>=1)
__device__ __forceinline__ float bil_profile(int j, int lo, int hi, int g) {
    float s  = (j + 0.5f) * (float)g / 100.0f - 0.5f;
    float fs = floorf(s);
    float w  = s - fs;
    int f0 = (int)fs, f1 = f0 + 1;
    if (f0 < 0) f0 = 0; if (f0 > g-1) f0 = g-1;
    if (f1 < 0) f1 = 0; if (f1 > g-1) f1 = g-1;
    float v0 = (f0 >= lo && f0 < hi) ? 1.f : 0.f;
    float v1 = (f1 >= lo && f1 < hi) ? 1.f : 0.f;
    return v0 * (1.f - w) + v1 * w;
}

// block 0: composed 5x5 kernel; blocks 1..NS: per-sample profile meta;
// block NS+1: human profiles
__global__ void k_setup(const int* ox, const int* oy, const int* ow, const int* oh,
                        const int* pgh, const int* pgw,
                        const float* c1w, const float* c2w) {
    int b = blockIdx.x, t = threadIdx.x;
    if (b == 0) {
        if (t < 32) {
            int o = t;
            float g5l[25];
            #pragma unroll
            for (int i = 0; i < 25; i++) g5l[i] = 0.f;
            for (int m = 0; m < 16; m++) {
                float w1c[9], w2c[9];
                #pragma unroll
                for (int i = 0; i < 9; i++) w1c[i] = c1w[(m*2+1)*9 + i];  // in-ch 1
                #pragma unroll
                for (int i = 0; i < 9; i++) w2c[i] = c2w[(o*16+m)*9 + i];
                #pragma unroll
                for (int ky = 0; ky < 3; ky++)
                #pragma unroll
                for (int kx = 0; kx < 3; kx++)
                #pragma unroll
                for (int ey = 0; ey < 3; ey++)
                #pragma unroll
                for (int ex = 0; ex < 3; ex++) {
                    int a = 4 - (ky + ey), bb = 4 - (kx + ex);
                    g5l[a*5 + bb] += w1c[ky*3+kx] * w2c[ey*3+ex];
                }
            }
            for (int i = 0; i < 25; i++) d_g5[o*25 + i] = g5l[i];
        }
    } else if (b <= NS) {
        __shared__ float py[G], px[G];
        int s = b - 1;
        int gh = *pgh, gw = *pgw;
        if (t < G) {
            py[t] = bil_profile(t, oy[s], oy[s] + oh[s], gh);
            px[t] = bil_profile(t, ox[s], ox[s] + ow[s], gw);
        }
        __syncthreads();
        if (t == 0) {
            int iL = -1, iR = -1;
            for (int i = 0; i < G; i++) if (py[i] != 0.f) { if (iL < 0) iL = i; iR = i; }
            float ay = 0.f, by = 0.f;
            if (iL >= 0) { ay = py[iL]; by = (iR > iL) ? py[iR] : 0.f; } else { iL = 0; iR = 0; }
            d_mi[s*4+0] = iL; d_mi[s*4+1] = iR; d_mw[s*4+0] = ay; d_mw[s*4+1] = by;
            int jL = -1, jR = -1;
            for (int j = 0; j < G; j++) if (px[j] != 0.f) { if (jL < 0) jL = j; jR = j; }
            float ax = 0.f, bx = 0.f;
            if (jL >= 0) { ax = px[jL]; bx = (jR > jL) ? px[jR] : 0.f; } else { jL = 0; jR = 0; }
            d_mi[s*4+2] = jL; d_mi[s*4+3] = jR; d_mw[s*4+2] = ax; d_mw[s*4+3] = bx;
        }
    } else {
        int gh = *pgh, gw = *pgw;
        if (t < G) {
            d_hy[t] = bil_profile(t, 0, 100, gh);
            d_hx[t] = bil_profile(t, 0, 100, gw);
        }
    }
}

// x1h = conv1((human,0)) + b1 ; human = hy (outer) hx
__global__ void k_x1h(const float* c1w, const float* c1b) {
    __shared__ float sw[16*9], sb[16];
    int y = blockIdx.x, t = threadIdx.x;
    for (int i = t; i < 144; i += 128) sw[i] = c1w[(i/9)*18 + (i%9)];  // in-ch 0
    if (t < 16) sb[t] = c1b[t];
    __syncthreads();
    if (t < G) {
        int x = t;
        float hyv[3], hxv[3];
        #pragma unroll
        for (int a = 0; a < 3; a++) {
            int yy = y - 1 + a; hyv[a] = (yy >= 0 && yy < G) ? d_hy[yy] : 0.f;
            int xx = x - 1 + a; hxv[a] = (xx >= 0 && xx < G) ? d_hx[xx] : 0.f;
        }
        for (int m = 0; m < 16; m++) {
            float acc = sb[m];
            #pragma unroll
            for (int a = 0; a < 3; a++)
            #pragma unroll
            for (int bb = 0; bb < 3; bb++) acc += sw[m*9 + a*3 + bb] * hyv[a] * hxv[bb];
            d_x1h[(m*G + y)*G + x] = acc;
        }
    }
}

// x2h = conv2(x1h) + b2
__global__ void k_x2h(const float* c2w, const float* c2b) {
    __shared__ float sw2[32*16*9];
    __shared__ float sb2[32];
    __shared__ float sx1[16*3*G];
    int y = blockIdx.x, t = threadIdx.x;
    for (int i = t; i < 4608; i += 128) sw2[i] = c2w[i];
    if (t < 32) sb2[t] = c2b[t];
    for (int i = t; i < 16*3*G; i += 128) {
        int m = i / (3*G), rem = i % (3*G), a = rem / G, x = rem % G;
        int yy = y - 1 + a;
        sx1[i] = (yy >= 0 && yy < G) ? d_x1h[(m*G + yy)*G + x] : 0.f;
    }
    __syncthreads();
    if (t < G) {
        int x = t;
        float acc[32];
        #pragma unroll
        for (int o = 0; o < 32; o++) acc[o] = sb2[o];
        for (int m = 0; m < 16; m++) {
            float v[9];
            #pragma unroll
            for (int a = 0; a < 3; a++)
            #pragma unroll
            for (int bb = 0; bb < 3; bb++) {
                int xx = x - 1 + bb;
                v[a*3+bb] = (xx >= 0 && xx < G) ? sx1[(m*3 + a)*G + xx] : 0.f;
            }
            #pragma unroll
            for (int o = 0; o < 32; o++) {
                float s0 = acc[o];
                #pragma unroll
                for (int kk = 0; kk < 9; kk++) s0 += sw2[(o*16+m)*9 + kk] * v[kk];
                acc[o] = s0;
            }
        }
        for (int o = 0; o < 32; o++) d_x2h[(o*G + y)*G + x] = acc[o];
    }
}

// ---------------------------------------------------------------------------
// k_M: unchanged from the passing R16 version.
// ---------------------------------------------------------------------------
__global__ void __launch_bounds__(256) k_M(const float* __restrict__ P) {
    __shared__ float  smN[2][SMW];
    __shared__ float  smS[2][SMW];
    __shared__ float2 sg01[32*5];
    __shared__ float2 sg23[32*5];
    __shared__ float  sg4[32*5];
    __shared__ float  sred[256];
    int rt = blockIdx.x, f = blockIdx.y, t = threadIdx.x;
    int r0 = rt * TR2;
    const float* Pf = P + (size_t)f * 32 * G * G;

    for (int i = t; i < 160; i += 256) {
        int o = i / 5, u = i % 5;
        const float* g = d_g5 + o*25 + u*5;
        sg01[i] = make_float2(g[0], g[1]);
        sg23[i] = make_float2(g[2], g[3]);
        sg4[i]  = g[4];
    }
    for (int i = t; i < SMW; i += 256) {
        smN[0][i] = 0.f; smN[1][i] = 0.f; smS[0][i] = 0.f; smS[1][i] = 0.f;
    }
    __syncthreads();

    int  cg[3], crw[3];
    bool cv[3];
    #pragma unroll
    for (int c = 0; c < 3; c++) {
        int idx = t + c*256;
        int row = idx / 25, c4 = idx % 25;
        int gr  = r0 - 2 + row;
        cv[c]  = (idx < 600) && (gr >= 0) && (gr < G);
        cg[c]  = gr*G + c4*4;
        crw[c] = row*104 + 2 + c4*4;
    }

    auto load_buf = [&](int buf, int o) {
        const float* src = Pf + o*G*G;
        #pragma unroll
        for (int c = 0; c < 3; c++) {
            if (cv[c]) {
                float4 v = *(const float4*)(src + cg[c]);
                *(float2*)&smN[buf][crw[c]]     = make_float2(v.x, v.y);
                *(float2*)&smN[buf][crw[c] + 2] = make_float2(v.z, v.w);
                smS[buf][crw[c] + 1] = v.x;
                *(float2*)&smS[buf][crw[c] + 2] = make_float2(v.y, v.z);
                smS[buf][crw[c] + 4] = v.w;
            }
        }
    };

    load_buf(0, 0);

    bool act = t < 200;
    int h = t / 100, j = t % 100;
    bool odd = (j & 1);
    int rowbase = h*10*104 + (odd ? (j + 1) : j);

    unsigned long long acc2[10];
    float accS[10];
    #pragma unroll
    for (int r = 0; r < 10; r++) { acc2[r] = 0ULL; accS[r] = 0.f; }
    float cacc = 0.f;

    __syncthreads();

    for (int o = 0; o < 32; o++) {
        int buf = o & 1;
        if (o + 1 < 32) load_buf(buf ^ 1, o + 1);
        if (act) {
            unsigned long long g01r[5], g23r[5];
            float g4r[5];
            #pragma unroll
            for (int u = 0; u < 5; u++) {
                g01r[u] = *(const unsigned long long*)&sg01[o*5 + u];
                g23r[u] = *(const unsigned long long*)&sg23[o*5 + u];
                g4r[u]  = sg4[o*5 + u];
            }
            const float* base = odd ? &smS[buf][rowbase] : &smN[buf][rowbase];
            const float* x2b  = d_x2h + (o*G + r0 + h*10)*G + j;
            #pragma unroll
            for (int k = 0; k < 14; k++) {
                unsigned long long p01 = *(const unsigned long long*)(base + k*104);
                unsigned long long p23 = *(const unsigned long long*)(base + k*104 + 2);
                float c4v = base[k*104 + 4];
                #pragma unroll
                for (int u = 0; u < 5; u++) {
                    int r = k - u;
                    if (r >= 0 && r < 10) {
                        acc2[r] = ffma2(g01r[u], p01, acc2[r]);
                        acc2[r] = ffma2(g23r[u], p23, acc2[r]);
                        accS[r] = fmaf(g4r[u], c4v, accS[r]);
                    }
                }
                if (k >= 2 && k <= 11) {
                    cacc = fmaf(f2lo(p23), x2b[(k - 2)*G], cacc);
                }
            }
        }
        __syncthreads();
    }

    if (act) {
        #pragma unroll
        for (int r = 0; r < 10; r++)
            d_M[(f*G + r0 + h*10 + r)*G + j] = f2lo(acc2[r]) + f2hi(acc2[r]) + accS[r];
    }
    sred[t] = act ? cacc : 0.f;
    __syncthreads();
    for (int s = 128; s > 0; s >>= 1) { if (t < s) sred[t] += sred[t + s]; __syncthreads(); }
    if (t == 0) d_cpart[f*NRT + rt] = sred[0];
}

// ---------------------------------------------------------------------------
// k_border (REWRITTEN): border P lines staged in smem once; T computed from
// smem; identical math to the passing version. 4 phases: N, S, W, E.
//   N/S: T[m][qq]  = sum_o sum_e w[o][m][e] * brow[o][qq - e + 2], qq in [0,102)
//   W/E: T[m][p+1] = sum_o sum_e w[o][m][e] * brow[o][p - e + 3], p in [0,100)
//        (T[m][0] and T[m][101] stay 0 == the original validity window)
// ---------------------------------------------------------------------------
__global__ void __launch_bounds__(256) k_border(const float* __restrict__ P,
                                                const float* __restrict__ c1w,
                                                const float* __restrict__ c2w) {
    __shared__ float brow[32][104];
    __shared__ float T[16][104];
    __shared__ float w[32][16][3];
    int f = blockIdx.x, t = threadIdx.x;
    const float* Pf = P + (size_t)f * 32 * G * G;

    #pragma unroll
    for (int phase = 0; phase < 4; phase++) {
        __syncthreads();  // previous phase's readers done before overwrite
        // zero T fully + brow pads; load brow data + weights (disjoint writes)
        for (int i = t; i < 16*104; i += 256) ((float*)T)[i] = 0.f;
        if (t < 32) {
            brow[t][0] = 0.f; brow[t][1] = 0.f; brow[t][102] = 0.f; brow[t][103] = 0.f;
        }
        for (int i = t; i < 32*100; i += 256) {
            int o = i / 100, c = i % 100;
            float v;
            if      (phase == 0) v = Pf[(o*G + 0)*G + c];
            else if (phase == 1) v = Pf[(o*G + (G-1))*G + c];
            else if (phase == 2) v = Pf[(o*G + c)*G + 0];
            else                 v = Pf[(o*G + c)*G + (G-1)];
            brow[o][2 + c] = v;
        }
        for (int i = t; i < 32*16*3; i += 256) {
            int o = i / 48, m = (i / 3) % 16, e = i % 3;
            int widx;
            if      (phase == 0) widx = (o*16+m)*9 + 0*3 + e;
            else if (phase == 1) widx = (o*16+m)*9 + 2*3 + e;
            else if (phase == 2) widx = (o*16+m)*9 + e*3 + 0;
            else                 widx = (o*16+m)*9 + e*3 + 2;
            w[o][m][e] = c2w[widx];
        }
        __syncthreads();
        if (phase < 2) {
            for (int i = t; i < 16*102; i += 256) {
                int m = i / 102, qq = i % 102;
                float acc = 0.f;
                for (int o = 0; o < 32; o++) {
                    #pragma unroll
                    for (int e = 0; e < 3; e++)
                        acc = fmaf(w[o][m][e], brow[o][qq - e + 2], acc);
                }
                T[m][qq] = acc;
            }
        } else {
            for (int i = t; i < 16*100; i += 256) {
                int m = i / 100, p = i % 100;
                float acc = 0.f;
                for (int o = 0; o < 32; o++) {
                    #pragma unroll
                    for (int e = 0; e < 3; e++)
                        acc = fmaf(w[o][m][e], brow[o][p - e + 3], acc);
                }
                T[m][p + 1] = acc;
            }
        }
        __syncthreads();
        if (t < G) {
            float corr = 0.f;
            if (phase == 0) {
                int j = t;
                for (int m = 0; m < 16; m++)
                    #pragma unroll
                    for (int kx = 0; kx < 3; kx++)
                        corr = fmaf(c1w[(m*2+1)*9 + 2*3 + kx], T[m][j - kx + 2], corr);
                d_M[(f*G + 0)*G + j] -= corr;
            } else if (phase == 1) {
                int j = t;
                for (int m = 0; m < 16; m++)
                    #pragma unroll
                    for (int kx = 0; kx < 3; kx++)
                        corr = fmaf(c1w[(m*2+1)*9 + 0*3 + kx], T[m][j - kx + 2], corr);
                d_M[(f*G + (G-1))*G + j] -= corr;
            } else if (phase == 2) {
                int i = t;
                for (int m = 0; m < 16; m++)
                    #pragma unroll
                    for (int ky = 0; ky < 3; ky++)
                        corr = fmaf(c1w[(m*2+1)*9 + ky*3 + 2], T[m][i - ky + 2], corr);
                d_M[(f*G + i)*G + 0] -= corr;
            } else {
                int i = t;
                for (int m = 0; m < 16; m++)
                    #pragma unroll
                    for (int ky = 0; ky < 3; ky++)
                        corr = fmaf(c1w[(m*2+1)*9 + ky*3 + 0], T[m][i - ky + 2], corr);
                d_M[(f*G + i)*G + (G-1)] -= corr;
            }
        }
    }
}

// inclusive 2-D SAT per f, in shared memory
__global__ void k_prefix() {
    __shared__ float sm[G][G + 1];
    int f = blockIdx.x, t = threadIdx.x;
    for (int i = t; i < G*G; i += 128) sm[i / G][i % G] = d_M[f*G*G + i];
    __syncthreads();
    if (t < G) {
        float r = 0.f;
        for (int j = 0; j < G; j++) { r += sm[t][j]; sm[t][j] = r; }
    }
    __syncthreads();
    if (t < G) {
        float r = 0.f;
        for (int i = 0; i < G; i++) { r += sm[i][t]; sm[i][t] = r; }
    }
    __syncthreads();
    for (int i = t; i < G*G; i += 128) d_S[f*G*G + i] = sm[i / G][i % G];
}

__device__ __forceinline__ float satv(const float* base, int i, int j) {
    return (i < 0 || j < 0) ? 0.f : base[i*G + j];
}
__device__ __forceinline__ float rectsum(const float* base, int a, int b, int c, int d) {
    if (a > b || c > d) return 0.f;
    return satv(base, b, d) - satv(base, a-1, d) - satv(base, b, c-1) + satv(base, a-1, c-1);
}

// out[s,f] = const[f] + py^T M_f px via SAT
__global__ void k_eval(const float* __restrict__ pb, float* __restrict__ out) {
    int s = blockIdx.x, f = threadIdx.x;
    int   iL = d_mi[s*4+0], iR = d_mi[s*4+1], jL = d_mi[s*4+2], jR = d_mi[s*4+3];
    float ay = d_mw[s*4+0], by = d_mw[s*4+1], ax = d_mw[s*4+2], bx = d_mw[s*4+3];
    const float* base = d_S + (size_t)f * G * G;
    int i0 = iL + 1, i1 = iR - 1, j0 = jL + 1, j1 = jR - 1;
    float acc = rectsum(base, i0, i1, j0, j1);
    acc += ay * rectsum(base, iL, iL, j0, j1) + by * rectsum(base, iR, iR, j0, j1);
    acc += ax * rectsum(base, i0, i1, jL, jL) + bx * rectsum(base, i0, i1, jR, jR);
    acc += ay*ax * rectsum(base, iL, iL, jL, jL) + ay*bx * rectsum(base, iL, iL, jR, jR)
         + by*ax * rectsum(base, iR, iR, jL, jL) + by*bx * rectsum(base, iR, iR, jR, jR);
    float cs = pb[f];
    #pragma unroll
    for (int r = 0; r < NRT; r++) cs += d_cpart[f*NRT + r];
    out[s*NF + f] = cs + acc;
}

extern "C" void kernel_launch(void* const* d_in, const int* in_sizes, int n_in,
                              void* d_out, int out_size) {
    const int*   ox  = (const int*)d_in[0];
    const int*   oy  = (const int*)d_in[1];
    const int*   ow  = (const int*)d_in[2];
    const int*   oh  = (const int*)d_in[3];
    const int*   gh  = (const int*)d_in[4];
    const int*   gw  = (const int*)d_in[5];
    const float* c1w = (const float*)d_in[6];
    const float* c1b = (const float*)d_in[7];
    const float* c2w = (const float*)d_in[8];
    const float* c2b = (const float*)d_in[9];
    const float* pw  = (const float*)d_in[10];
    const float* pbb = (const float*)d_in[11];
    float* out = (float*)d_out;

    k_setup <<<NS + 2, 128>>>(ox, oy, ow, oh, gh, gw, c1w, c2w);
    k_x1h   <<<G, 128>>>(c1w, c1b);
    k_x2h   <<<G, 128>>>(c2w, c2b);
    k_M     <<<dim3(NRT, NF), 256>>>(pw);
    k_border<<<NF, 256>>>(pw, c1w, c2w);
    k_prefix<<<NF, 128>>>();
    k_eval  <<<NS, NF>>>(pbb, out);
}